// round 13
// baseline (speedup 1.0000x reference)
#include <cuda_runtime.h>
#include <cuda_fp16.h>
#include <cstdint>

#define THREADS 512
static constexpr int BATCH  = 131072;
static constexpr int DDIM   = 128;
static constexpr int TILE_M = 128;
static constexpr int NTILES = BATCH / TILE_M;   // 1024
static constexpr int PITCH  = 272;              // 128 fp16 (256B) + 16B pad -> conflict-free ldmatrix
static constexpr int ASEG   = 32 * PITCH;       // 8704B: one 32-row fp16 group buffer
static constexpr int RSEG   = 32 * 512;         // 16384B: one 32-row raw fp32 group buffer

// ---- SMEM layout (bytes). A: 4 groups x 2 fp16 buffers; raw: 4 groups x 1; B fp16; bias. ----
static constexpr int SM_A    = 0;               // 4 * 2 * 8704 = 69632
static constexpr int SM_RAW  = 69632;           // 4 * 16384 = 65536
static constexpr int SM_B    = 135168;          // 256 x PITCH = 69632
static constexpr int SM_BIAS = 204800;          // 256 floats = 1024
static constexpr int SMEM_TOTAL = 205824;

// ---------------- helpers ----------------
__device__ __forceinline__ uint32_t smem_u32(const void* p){
    uint32_t a;
    asm("{ .reg .u64 t; cvta.to.shared.u64 t, %1; cvt.u32.u64 %0, t; }" : "=r"(a) : "l"(p));
    return a;
}
__device__ __forceinline__ void ldsm4(uint32_t* r, uint32_t addr){
    asm volatile("ldmatrix.sync.aligned.m8n8.x4.shared.b16 {%0,%1,%2,%3}, [%4];"
        : "=r"(r[0]), "=r"(r[1]), "=r"(r[2]), "=r"(r[3]) : "r"(addr));
}
__device__ __forceinline__ void mma16816(float* c, const uint32_t* a, uint32_t b0, uint32_t b1){
    asm("mma.sync.aligned.m16n8k16.row.col.f32.f16.f16.f32 "
        "{%0,%1,%2,%3}, {%4,%5,%6,%7}, {%8,%9}, {%0,%1,%2,%3};"
        : "+f"(c[0]), "+f"(c[1]), "+f"(c[2]), "+f"(c[3])
        : "r"(a[0]), "r"(a[1]), "r"(a[2]), "r"(a[3]), "r"(b0), "r"(b1));
}
__device__ __forceinline__ uint32_t pack_h2(float lo, float hi){
    __half2 h = __floats2half2_rn(lo, hi);
    return *reinterpret_cast<uint32_t*>(&h);
}
__device__ __forceinline__ void group_bar(int id){
    asm volatile("bar.sync %0, 128;" :: "r"(id) : "memory");
}
__device__ __forceinline__ void cp_async16(uint32_t saddr, const void* gptr){
    asm volatile("cp.async.cg.shared.global [%0], [%1], 16;" :: "r"(saddr), "l"(gptr) : "memory");
}
__device__ __forceinline__ void cp_commit(){ asm volatile("cp.async.commit_group;" ::: "memory"); }
__device__ __forceinline__ void cp_wait0(){ asm volatile("cp.async.wait_group 0;" ::: "memory"); }
__device__ __forceinline__ float4 lds128(uint32_t addr){
    float4 v;
    asm volatile("ld.shared.v4.f32 {%0,%1,%2,%3}, [%4];"
        : "=f"(v.x), "=f"(v.y), "=f"(v.z), "=f"(v.w) : "r"(addr));
    return v;
}
__device__ __forceinline__ float2 lds64(uint32_t addr){
    float2 v;
    asm volatile("ld.shared.v2.f32 {%0,%1}, [%2];" : "=f"(v.x), "=f"(v.y) : "r"(addr));
    return v;
}

// ---------------- group tile helpers (each group owns 32 rows of the tile) ----------------
// gt in [0,128): thread index within group; each thread handles 8 float4 of the 32x128 slice.
__device__ __forceinline__ void issue_cp_group(const float* __restrict__ state, int t, int wm, int gt,
                                               uint32_t raw_base){
    const float4* p = reinterpret_cast<const float4*>(state)
                    + (size_t)t * (TILE_M * DDIM / 4) + (size_t)(wm * 32) * (DDIM / 4);
    #pragma unroll
    for (int k = 0; k < 8; k++)
        cp_async16(raw_base + (uint32_t)(gt + 128 * k) * 16, p + gt + 128 * k);
    cp_commit();
}

// convert raw fp32 slice (smem) -> fp16 A buffer (smem).
__device__ __forceinline__ void convert_group(char* sm, uint32_t sbase, uint32_t raw_off,
                                              uint32_t aseg_off, int gt){
    #pragma unroll
    for (int k = 0; k < 8; k++){
        int j  = gt + 128 * k;                // float4 index within 32x128 group slice
        int r  = j >> 5;                      // local row [0,32)
        int cb = (j & 31) * 8;                // byte col within 256B of fp16 data
        float4 f = lds128(sbase + raw_off + (uint32_t)j * 16);
        uint32_t off = aseg_off + (uint32_t)r * PITCH + cb;
        uint32_t h0 = pack_h2(f.x, f.y);
        uint32_t h1 = pack_h2(f.z, f.w);
        *reinterpret_cast<uint2*>(sm + off) = make_uint2(h0, h1);
    }
}

// ---------------- kernel ----------------
__global__ void __launch_bounds__(THREADS, 1)
lfm_kernel(const float* __restrict__ state, const float* __restrict__ Wt,
           const float* __restrict__ bias,  float* __restrict__ out)
{
    extern __shared__ char sm[];
    uint32_t sbase = smem_u32(sm);
    const int tid  = threadIdx.x;
    const int wid  = tid >> 5;
    const int lane = tid & 31;
    // Group = contiguous warp quartet (wid>>2): its 4 warps land on SMSPs 0..3,
    // so every SMSP hosts one warp from each pipeline group (phase interleaving).
    const int wm   = wid >> 2;      // pipeline group / m-block (32 rows each)
    const int wn   = wid & 3;       // warp n-block (64 cols each)
    const int gt   = tid & 127;     // thread index within group [0,128)

    // ---- one-time: W[n][o][d] -> fp16 B smem (row index = o*128+n, k=d), bias to smem ----
    for (int idx = tid; idx < 128 * 128; idx += THREADS){
        int n = idx >> 7, d = idx & 127;
        #pragma unroll
        for (int o = 0; o < 2; o++){
            float w = Wt[(size_t)n * 256 + o * 128 + d];
            uint32_t off = (uint32_t)(o * 128 + n) * PITCH + d * 2;
            *reinterpret_cast<__half*>(sm + SM_B + off) = __float2half_rn(w);
        }
    }
    for (int idx = tid; idx < 256; idx += THREADS){
        int o = idx >> 7, n = idx & 127;
        reinterpret_cast<float*>(sm + SM_BIAS)[idx] = bias[n * 2 + o];
    }

    // per-lane ldmatrix sub-offsets
    const uint32_t aoff = (uint32_t)((lane & 7) + ((lane >> 3) & 1) * 8) * PITCH + ((lane >> 4) & 1) * 16;
    const uint32_t boff = (uint32_t)((lane & 7) + ((lane >> 4) & 1) * 8) * PITCH + ((lane >> 3) & 1) * 16;
    const uint32_t aseg0    = (uint32_t)(SM_A + wm * 2 * ASEG);      // group fp16 buf 0 offset
    const uint32_t raw_off  = (uint32_t)(SM_RAW + wm * RSEG);        // group raw buf offset
    const uint32_t raw_base = sbase + raw_off;
    const uint32_t baseB    = sbase + SM_B + (uint32_t)(wn * 64) * PITCH + boff;

    const int bid = blockIdx.x, grid = gridDim.x;
    const int nt  = (NTILES - bid + grid - 1) / grid;   // >= 1 since grid <= NTILES

    // Prologue: async-load tile bid's slice, convert into buffer 0
    issue_cp_group(state, bid, wm, gt, raw_base);
    cp_wait0();
    convert_group(sm, sbase, raw_off, aseg0, gt);
    __syncthreads();   // covers W/bias init + all groups' first convert

    const int o_half = wn >> 1;
    const size_t out_half = (size_t)BATCH * DDIM;
    const int barid = 1 + wm;
    // bias smem address base for this warp's epilogue (per-nj stride 8 floats)
    const uint32_t bias_base = sbase + (uint32_t)SM_BIAS
                             + (uint32_t)((o_half << 7) + (wn & 1) * 64 + 2 * (lane & 3)) * 4;

    int cur = 0;
    for (int i = 0; i < nt; i++){
        const int  t   = bid + i * grid;
        const bool nxt = (i + 1) < nt;

        // Kick next tile's async copy NOW: the copy engine runs under the whole K-loop.
        if (nxt) issue_cp_group(state, t + grid, wm, gt, raw_base);

        const uint32_t bA = sbase + aseg0 + (uint32_t)cur * ASEG + aoff;

        float acc[2][8][4];
        #pragma unroll
        for (int mt = 0; mt < 2; mt++)
            #pragma unroll
            for (int nj = 0; nj < 8; nj++)
                #pragma unroll
                for (int e = 0; e < 4; e++) acc[mt][nj][e] = 0.f;

        // ---- K loop: 8 steps of k16, A fragments software-pipelined one ks ahead ----
        uint32_t aP[2][8];                       // double-buffered A frags: [buf][a0(4)|a1(4)]
        ldsm4(&aP[0][0], bA);
        ldsm4(&aP[0][4], bA + 16 * PITCH);
        #pragma unroll
        for (int ks = 0; ks < 8; ks++){
            const int cb = ks & 1;
            if (ks < 7){                         // prefetch ks+1 A frags before ks MMAs
                ldsm4(&aP[cb ^ 1][0], bA + (ks + 1) * 32);
                ldsm4(&aP[cb ^ 1][4], bA + 16 * PITCH + (ks + 1) * 32);
            }
            const uint32_t* a0 = &aP[cb][0];
            const uint32_t* a1 = &aP[cb][4];
            #pragma unroll
            for (int np = 0; np < 4; np++){      // pairs of n8 tiles (independent chains)
                uint32_t bw[4];
                ldsm4(bw, baseB + (uint32_t)(np * 16) * PITCH + ks * 32);
                mma16816(acc[0][2*np],   a0, bw[0], bw[1]);
                mma16816(acc[1][2*np],   a1, bw[0], bw[1]);
                mma16816(acc[0][2*np+1], a0, bw[2], bw[3]);
                mma16816(acc[1][2*np+1], a1, bw[2], bw[3]);
            }
        }

        // ---- convert + barrier FIRST: BAR.SYNC is defer-blocking on sm_103a, so the
        //      epilogue STGs below execute during the barrier wait; the block only
        //      fires at the next K-loop's first LDSM (which needs the protected smem).
        if (nxt){
            cp_wait0();                                           // copy finished under K-loop
            convert_group(sm, sbase, raw_off, aseg0 + (uint32_t)(cur ^ 1) * ASEG, gt);
            group_bar(barid);
        }

        // ---- epilogue: bias (smem) + direct STG.64 (fire-and-forget; overlaps barrier). ----
        {
            const int colw  = (wn & 1) * 64;
            const int rbase = wm * 32 + (lane >> 2);
            float* outp = out + (o_half ? out_half : 0) + ((size_t)t * TILE_M) * DDIM;
            #pragma unroll
            for (int nj = 0; nj < 8; nj++){
                float2 bv = lds64(bias_base + (uint32_t)nj * 32);   // {b0, b1} for this nj
                const int cg = colw + nj * 8 + 2 * (lane & 3);
                #pragma unroll
                for (int mt = 0; mt < 2; mt++){
                    float* p0 = outp + (size_t)(rbase + mt * 16) * DDIM + cg;
                    float* p1 = p0 + 8 * DDIM;
                    *reinterpret_cast<float2*>(p0) = make_float2(acc[mt][nj][0] + bv.x, acc[mt][nj][1] + bv.y);
                    *reinterpret_cast<float2*>(p1) = make_float2(acc[mt][nj][2] + bv.x, acc[mt][nj][3] + bv.y);
                }
            }
        }

        cur ^= 1;
    }
}

extern "C" void kernel_launch(void* const* d_in, const int* in_sizes, int n_in,
                              void* d_out, int out_size){
    (void)in_sizes; (void)n_in; (void)out_size;
    const float* state = (const float*)d_in[0];
    const float* W     = (const float*)d_in[1];
    const float* b     = (const float*)d_in[2];
    float* out = (float*)d_out;

    int dev = 0, sms = 148;
    cudaGetDevice(&dev);
    cudaDeviceGetAttribute(&sms, cudaDevAttrMultiProcessorCount, dev);
    if (sms < 1) sms = 148;
    if (sms > NTILES) sms = NTILES;

    cudaFuncSetAttribute(lfm_kernel, cudaFuncAttributeMaxDynamicSharedMemorySize, SMEM_TOTAL);
    lfm_kernel<<<sms, THREADS, SMEM_TOTAL>>>(state, W, b, out);
}

// round 14
// speedup vs baseline: 1.0187x; 1.0187x over previous
#include <cuda_runtime.h>
#include <cuda_fp16.h>
#include <cstdint>

#define THREADS 512
static constexpr int BATCH  = 131072;
static constexpr int DDIM   = 128;
static constexpr int TILE_M = 128;
static constexpr int NTILES = BATCH / TILE_M;   // 1024
static constexpr int PITCH  = 272;              // 128 fp16 (256B) + 16B pad -> conflict-free ldmatrix
static constexpr int ASEG   = 32 * PITCH;       // 8704B: one 32-row fp16 group buffer
static constexpr int RSEG   = 32 * 512;         // 16384B: one 32-row raw fp32 group buffer

// ---- SMEM layout (bytes). A: 4 groups x 2 fp16 buffers; raw: 4 groups x 1; B fp16; bias. ----
static constexpr int SM_A    = 0;               // 4 * 2 * 8704 = 69632
static constexpr int SM_RAW  = 69632;           // 4 * 16384 = 65536
static constexpr int SM_B    = 135168;          // 256 x PITCH = 69632
static constexpr int SM_BIAS = 204800;          // 256 floats = 1024
static constexpr int SMEM_TOTAL = 205824;

// ---------------- helpers ----------------
__device__ __forceinline__ uint32_t smem_u32(const void* p){
    uint32_t a;
    asm("{ .reg .u64 t; cvta.to.shared.u64 t, %1; cvt.u32.u64 %0, t; }" : "=r"(a) : "l"(p));
    return a;
}
__device__ __forceinline__ void ldsm4(uint32_t* r, uint32_t addr){
    asm volatile("ldmatrix.sync.aligned.m8n8.x4.shared.b16 {%0,%1,%2,%3}, [%4];"
        : "=r"(r[0]), "=r"(r[1]), "=r"(r[2]), "=r"(r[3]) : "r"(addr));
}
__device__ __forceinline__ void mma16816(float* c, const uint32_t* a, uint32_t b0, uint32_t b1){
    asm("mma.sync.aligned.m16n8k16.row.col.f32.f16.f16.f32 "
        "{%0,%1,%2,%3}, {%4,%5,%6,%7}, {%8,%9}, {%0,%1,%2,%3};"
        : "+f"(c[0]), "+f"(c[1]), "+f"(c[2]), "+f"(c[3])
        : "r"(a[0]), "r"(a[1]), "r"(a[2]), "r"(a[3]), "r"(b0), "r"(b1));
}
__device__ __forceinline__ uint32_t pack_h2(float lo, float hi){
    __half2 h = __floats2half2_rn(lo, hi);
    return *reinterpret_cast<uint32_t*>(&h);
}
__device__ __forceinline__ void group_bar(int id){
    asm volatile("bar.sync %0, 128;" :: "r"(id) : "memory");
}
__device__ __forceinline__ void cp_async16(uint32_t saddr, const void* gptr){
    asm volatile("cp.async.cg.shared.global [%0], [%1], 16;" :: "r"(saddr), "l"(gptr) : "memory");
}
__device__ __forceinline__ void cp_commit(){ asm volatile("cp.async.commit_group;" ::: "memory"); }
__device__ __forceinline__ void cp_wait0(){ asm volatile("cp.async.wait_group 0;" ::: "memory"); }
__device__ __forceinline__ float4 lds128(uint32_t addr){
    float4 v;
    asm volatile("ld.shared.v4.f32 {%0,%1,%2,%3}, [%4];"
        : "=f"(v.x), "=f"(v.y), "=f"(v.z), "=f"(v.w) : "r"(addr));
    return v;
}
__device__ __forceinline__ void stg64_cs(float* p, float x, float y){
    asm volatile("st.global.cs.v2.f32 [%0], {%1, %2};" :: "l"(p), "f"(x), "f"(y) : "memory");
}

// ---------------- group tile helpers (each group owns 32 rows of the tile) ----------------
// gt in [0,128): thread index within group; each thread handles 8 float4 of the 32x128 slice.
__device__ __forceinline__ void issue_cp_group(const float* __restrict__ state, int t, int wm, int gt,
                                               uint32_t raw_base){
    const float4* p = reinterpret_cast<const float4*>(state)
                    + (size_t)t * (TILE_M * DDIM / 4) + (size_t)(wm * 32) * (DDIM / 4);
    #pragma unroll
    for (int k = 0; k < 8; k++)
        cp_async16(raw_base + (uint32_t)(gt + 128 * k) * 16, p + gt + 128 * k);
    cp_commit();
}

// one step (of 8) of the raw fp32 -> fp16 A-buffer conversion.
__device__ __forceinline__ void convert_step(char* sm, uint32_t sbase, uint32_t raw_off,
                                             uint32_t aseg_off, int gt, int k){
    int j  = gt + 128 * k;                // float4 index within 32x128 group slice
    int r  = j >> 5;                      // local row [0,32)
    int cb = (j & 31) * 8;                // byte col within 256B of fp16 data
    float4 f = lds128(sbase + raw_off + (uint32_t)j * 16);
    uint32_t off = aseg_off + (uint32_t)r * PITCH + cb;
    *reinterpret_cast<uint2*>(sm + off) = make_uint2(pack_h2(f.x, f.y), pack_h2(f.z, f.w));
}

__device__ __forceinline__ void convert_group(char* sm, uint32_t sbase, uint32_t raw_off,
                                              uint32_t aseg_off, int gt){
    #pragma unroll
    for (int k = 0; k < 8; k++) convert_step(sm, sbase, raw_off, aseg_off, gt, k);
}

// ---------------- kernel ----------------
__global__ void __launch_bounds__(THREADS, 1)
lfm_kernel(const float* __restrict__ state, const float* __restrict__ Wt,
           const float* __restrict__ bias,  float* __restrict__ out)
{
    extern __shared__ char sm[];
    uint32_t sbase = smem_u32(sm);
    const int tid  = threadIdx.x;
    const int wid  = tid >> 5;
    const int lane = tid & 31;
    // Group = contiguous warp quartet (wid>>2): its 4 warps land on SMSPs 0..3,
    // so every SMSP hosts one warp from each pipeline group (phase interleaving).
    const int wm   = wid >> 2;      // pipeline group / m-block (32 rows each)
    const int wn   = wid & 3;       // warp n-block (64 cols each)
    const int gt   = tid & 127;     // thread index within group [0,128)

    // ---- one-time: W[n][o][d] -> fp16 B smem (row index = o*128+n, k=d), bias to smem ----
    for (int idx = tid; idx < 128 * 128; idx += THREADS){
        int n = idx >> 7, d = idx & 127;
        #pragma unroll
        for (int o = 0; o < 2; o++){
            float w = Wt[(size_t)n * 256 + o * 128 + d];
            uint32_t off = (uint32_t)(o * 128 + n) * PITCH + d * 2;
            *reinterpret_cast<__half*>(sm + SM_B + off) = __float2half_rn(w);
        }
    }
    for (int idx = tid; idx < 256; idx += THREADS){
        int o = idx >> 7, n = idx & 127;
        reinterpret_cast<float*>(sm + SM_BIAS)[idx] = bias[n * 2 + o];
    }

    // per-lane ldmatrix sub-offsets
    const uint32_t aoff = (uint32_t)((lane & 7) + ((lane >> 3) & 1) * 8) * PITCH + ((lane >> 4) & 1) * 16;
    const uint32_t boff = (uint32_t)((lane & 7) + ((lane >> 4) & 1) * 8) * PITCH + ((lane >> 3) & 1) * 16;
    const uint32_t aseg0    = (uint32_t)(SM_A + wm * 2 * ASEG);      // group fp16 buf 0 offset
    const uint32_t raw_off  = (uint32_t)(SM_RAW + wm * RSEG);        // group raw buf offset
    const uint32_t raw_base = sbase + raw_off;
    const uint32_t baseB    = sbase + SM_B + (uint32_t)(wn * 64) * PITCH + boff;

    const int bid = blockIdx.x, grid = gridDim.x;
    const int nt  = (NTILES - bid + grid - 1) / grid;   // >= 1 since grid <= NTILES

    // Prologue: async-load tile bid's slice, convert into buffer 0
    issue_cp_group(state, bid, wm, gt, raw_base);
    cp_wait0();
    convert_group(sm, sbase, raw_off, aseg0, gt);
    __syncthreads();   // covers W/bias init + all groups' first convert

    // Bias fragments -> registers (constant across tiles; proven best in R12)
    const int o_half = wn >> 1;
    float bR0[8], bR1[8];
    {
        const float* bias_sm = reinterpret_cast<const float*>(sm + SM_BIAS);
        #pragma unroll
        for (int nj = 0; nj < 8; nj++){
            int cgb = (wn & 1) * 64 + nj * 8 + 2 * (lane & 3) + (o_half << 7);
            bR0[nj] = bias_sm[cgb];
            bR1[nj] = bias_sm[cgb + 1];
        }
    }

    const size_t out_half = (size_t)BATCH * DDIM;
    const int barid = 1 + wm;

    int cur = 0;
    for (int i = 0; i < nt; i++){
        const int  t   = bid + i * grid;
        const bool nxt = (i + 1) < nt;

        // Kick next tile's async copy NOW: the copy engine runs under the whole K-loop.
        if (nxt) issue_cp_group(state, t + grid, wm, gt, raw_base);

        const uint32_t bA   = sbase + aseg0 + (uint32_t)cur * ASEG + aoff;
        const uint32_t aNxt = aseg0 + (uint32_t)(cur ^ 1) * ASEG;

        float acc[2][8][4];
        #pragma unroll
        for (int mt = 0; mt < 2; mt++)
            #pragma unroll
            for (int nj = 0; nj < 8; nj++)
                #pragma unroll
                for (int e = 0; e < 4; e++) acc[mt][nj][e] = 0.f;

        // ---- K loop: 8 steps of k16. Convert steps for the NEXT tile are interleaved
        //      into ks=4..7 (independent LSU/ALU work filling MMA dependency bubbles).
        #pragma unroll
        for (int ks = 0; ks < 8; ks++){
            uint32_t a0[4], a1[4];
            ldsm4(a0, bA + ks * 32);
            ldsm4(a1, bA + 16 * PITCH + ks * 32);
            #pragma unroll
            for (int np = 0; np < 4; np++){        // pairs of n8 tiles
                uint32_t bw[4];
                ldsm4(bw, baseB + (uint32_t)(np * 16) * PITCH + ks * 32);
                mma16816(acc[0][2*np],   a0, bw[0], bw[1]);
                mma16816(acc[1][2*np],   a1, bw[0], bw[1]);
                mma16816(acc[0][2*np+1], a0, bw[2], bw[3]);
                mma16816(acc[1][2*np+1], a1, bw[2], bw[3]);
            }
            if (nxt){
                if (ks == 3) cp_wait0();           // copy issued at tile start: long done
                if (ks >= 4){
                    convert_step(sm, sbase, raw_off, aNxt, gt, 2 * (ks - 4));
                    convert_step(sm, sbase, raw_off, aNxt, gt, 2 * (ks - 4) + 1);
                }
            }
        }

        // ---- barrier immediately (defer-blocking): epilogue STGs below execute during
        //      the wait; the block only fires at the next K-loop's first LDSM.
        if (nxt) group_bar(barid);

        // ---- epilogue: bias + streaming STG.64 (write-once output -> evict-first). ----
        {
            const int colw  = (wn & 1) * 64;
            const int rbase = wm * 32 + (lane >> 2);
            float* outp = out + (o_half ? out_half : 0) + ((size_t)t * TILE_M) * DDIM;
            #pragma unroll
            for (int mt = 0; mt < 2; mt++){
                #pragma unroll
                for (int nj = 0; nj < 8; nj++){
                    const int cg = colw + nj * 8 + 2 * (lane & 3);
                    float b0 = bR0[nj], b1 = bR1[nj];
                    float* p0 = outp + (size_t)(rbase + mt * 16) * DDIM + cg;
                    float* p1 = p0 + 8 * DDIM;
                    stg64_cs(p0, acc[mt][nj][0] + b0, acc[mt][nj][1] + b1);
                    stg64_cs(p1, acc[mt][nj][2] + b0, acc[mt][nj][3] + b1);
                }
            }
        }

        cur ^= 1;
    }
}

extern "C" void kernel_launch(void* const* d_in, const int* in_sizes, int n_in,
                              void* d_out, int out_size){
    (void)in_sizes; (void)n_in; (void)out_size;
    const float* state = (const float*)d_in[0];
    const float* W     = (const float*)d_in[1];
    const float* b     = (const float*)d_in[2];
    float* out = (float*)d_out;

    int dev = 0, sms = 148;
    cudaGetDevice(&dev);
    cudaDeviceGetAttribute(&sms, cudaDevAttrMultiProcessorCount, dev);
    if (sms < 1) sms = 148;
    if (sms > NTILES) sms = NTILES;

    cudaFuncSetAttribute(lfm_kernel, cudaFuncAttributeMaxDynamicSharedMemorySize, SMEM_TOTAL);
    lfm_kernel<<<sms, THREADS, SMEM_TOTAL>>>(state, W, b, out);
}

// round 15
// speedup vs baseline: 1.1155x; 1.0950x over previous
#include <cuda_runtime.h>
#include <cuda_fp16.h>
#include <cstdint>

#define THREADS 512
static constexpr int BATCH  = 131072;
static constexpr int DDIM   = 128;
static constexpr int TILE_M = 128;
static constexpr int NTILES = BATCH / TILE_M;   // 1024
static constexpr int PITCH  = 272;              // 128 fp16 (256B) + 16B pad -> conflict-free ldmatrix
static constexpr int ASEG   = 32 * PITCH;       // 8704B: one 32-row fp16 group buffer
static constexpr int RSEG   = 32 * 512;         // 16384B: one 32-row raw fp32 group buffer

// ---- SMEM layout (bytes). A: 4 groups x 2 fp16 buffers; raw: 4 groups x 1; B fp16; bias. ----
static constexpr int SM_A    = 0;               // 4 * 2 * 8704 = 69632
static constexpr int SM_RAW  = 69632;           // 4 * 16384 = 65536
static constexpr int SM_B    = 135168;          // 256 x PITCH = 69632
static constexpr int SM_BIAS = 204800;          // 256 floats = 1024
static constexpr int SMEM_TOTAL = 205824;

// ---------------- helpers ----------------
__device__ __forceinline__ uint32_t smem_u32(const void* p){
    uint32_t a;
    asm("{ .reg .u64 t; cvta.to.shared.u64 t, %1; cvt.u32.u64 %0, t; }" : "=r"(a) : "l"(p));
    return a;
}
__device__ __forceinline__ void ldsm4(uint32_t* r, uint32_t addr){
    asm volatile("ldmatrix.sync.aligned.m8n8.x4.shared.b16 {%0,%1,%2,%3}, [%4];"
        : "=r"(r[0]), "=r"(r[1]), "=r"(r[2]), "=r"(r[3]) : "r"(addr));
}
__device__ __forceinline__ void mma16816(float* c, const uint32_t* a, uint32_t b0, uint32_t b1){
    asm("mma.sync.aligned.m16n8k16.row.col.f32.f16.f16.f32 "
        "{%0,%1,%2,%3}, {%4,%5,%6,%7}, {%8,%9}, {%0,%1,%2,%3};"
        : "+f"(c[0]), "+f"(c[1]), "+f"(c[2]), "+f"(c[3])
        : "r"(a[0]), "r"(a[1]), "r"(a[2]), "r"(a[3]), "r"(b0), "r"(b1));
}
__device__ __forceinline__ uint32_t pack_h2(float lo, float hi){
    __half2 h = __floats2half2_rn(lo, hi);
    return *reinterpret_cast<uint32_t*>(&h);
}
__device__ __forceinline__ void group_bar(int id){
    asm volatile("bar.sync %0, 128;" :: "r"(id) : "memory");
}
__device__ __forceinline__ void cp_async16(uint32_t saddr, const void* gptr){
    asm volatile("cp.async.cg.shared.global [%0], [%1], 16;" :: "r"(saddr), "l"(gptr) : "memory");
}
__device__ __forceinline__ void cp_commit(){ asm volatile("cp.async.commit_group;" ::: "memory"); }
__device__ __forceinline__ void cp_wait0(){ asm volatile("cp.async.wait_group 0;" ::: "memory"); }
__device__ __forceinline__ float4 lds128(uint32_t addr){
    float4 v;
    asm volatile("ld.shared.v4.f32 {%0,%1,%2,%3}, [%4];"
        : "=f"(v.x), "=f"(v.y), "=f"(v.z), "=f"(v.w) : "r"(addr));
    return v;
}

// ---------------- group tile helpers (each group owns 32 rows of the tile) ----------------
// gt in [0,128): thread index within group; each thread handles 8 float4 of the 32x128 slice.
__device__ __forceinline__ void issue_cp_group(const float* __restrict__ state, int t, int wm, int gt,
                                               uint32_t raw_base){
    const float4* p = reinterpret_cast<const float4*>(state)
                    + (size_t)t * (TILE_M * DDIM / 4) + (size_t)(wm * 32) * (DDIM / 4);
    #pragma unroll
    for (int k = 0; k < 8; k++)
        cp_async16(raw_base + (uint32_t)(gt + 128 * k) * 16, p + gt + 128 * k);
    cp_commit();
}

// convert raw fp32 slice (smem) -> fp16 A buffer (smem).
__device__ __forceinline__ void convert_group(char* sm, uint32_t sbase, uint32_t raw_off,
                                              uint32_t aseg_off, int gt){
    #pragma unroll
    for (int k = 0; k < 8; k++){
        int j  = gt + 128 * k;                // float4 index within 32x128 group slice
        int r  = j >> 5;                      // local row [0,32)
        int cb = (j & 31) * 8;                // byte col within 256B of fp16 data
        float4 f = lds128(sbase + raw_off + (uint32_t)j * 16);
        uint32_t off = aseg_off + (uint32_t)r * PITCH + cb;
        uint32_t h0 = pack_h2(f.x, f.y);
        uint32_t h1 = pack_h2(f.z, f.w);
        *reinterpret_cast<uint2*>(sm + off) = make_uint2(h0, h1);
    }
}

// Output-column -> B-smem-row permutation. Within every 16-column block, output
// column 16k + 4a + b (a,b in [0,4)) is stored at smem row 16k + 8*(b>>1) + 2a + (b&1).
// Result: the MMA fragment of lane q for tile pair {2k,2k+1} holds output columns
// {4q,4q+1,4q+2,4q+3} -> a single STG.128 per (mt,h,k). Pure column permutation of B,
// so the MMA math per element is unchanged.
__device__ __forceinline__ int perm_row(int n){
    int k16 = n & ~15;
    int a = (n >> 2) & 3, b = n & 3;
    return k16 + ((b >> 1) << 3) + 2 * a + (b & 1);
}

// ---------------- kernel ----------------
__global__ void __launch_bounds__(THREADS, 1)
lfm_kernel(const float* __restrict__ state, const float* __restrict__ Wt,
           const float* __restrict__ bias,  float* __restrict__ out)
{
    extern __shared__ char sm[];
    uint32_t sbase = smem_u32(sm);
    const int tid  = threadIdx.x;
    const int wid  = tid >> 5;
    const int lane = tid & 31;
    // Group = contiguous warp quartet (wid>>2): its 4 warps land on SMSPs 0..3,
    // so every SMSP hosts one warp from each pipeline group (phase interleaving).
    const int wm   = wid >> 2;      // pipeline group / m-block (32 rows each)
    const int wn   = wid & 3;       // warp n-block (64 cols each)
    const int gt   = tid & 127;     // thread index within group [0,128)

    // ---- one-time: W[n][o][d] -> fp16 B smem at PERMUTED row, bias to smem ----
    for (int idx = tid; idx < 128 * 128; idx += THREADS){
        int n = idx >> 7, d = idx & 127;
        #pragma unroll
        for (int o = 0; o < 2; o++){
            float w = Wt[(size_t)n * 256 + o * 128 + d];
            uint32_t off = (uint32_t)(o * 128 + perm_row(n)) * PITCH + d * 2;
            *reinterpret_cast<__half*>(sm + SM_B + off) = __float2half_rn(w);
        }
    }
    for (int idx = tid; idx < 256; idx += THREADS){
        int o = idx >> 7, n = idx & 127;
        reinterpret_cast<float*>(sm + SM_BIAS)[idx] = bias[n * 2 + o];   // bias_sm[o*128+n]
    }

    // per-lane ldmatrix sub-offsets
    const uint32_t aoff = (uint32_t)((lane & 7) + ((lane >> 3) & 1) * 8) * PITCH + ((lane >> 4) & 1) * 16;
    const uint32_t boff = (uint32_t)((lane & 7) + ((lane >> 4) & 1) * 8) * PITCH + ((lane >> 3) & 1) * 16;
    const uint32_t aseg0    = (uint32_t)(SM_A + wm * 2 * ASEG);      // group fp16 buf 0 offset
    const uint32_t raw_off  = (uint32_t)(SM_RAW + wm * RSEG);        // group raw buf offset
    const uint32_t raw_base = sbase + raw_off;
    const uint32_t baseB    = sbase + SM_B + (uint32_t)(wn * 64) * PITCH + boff;

    const int bid = blockIdx.x, grid = gridDim.x;
    const int nt  = (NTILES - bid + grid - 1) / grid;   // >= 1 since grid <= NTILES

    // Prologue: async-load tile bid's slice, convert into buffer 0
    issue_cp_group(state, bid, wm, gt, raw_base);
    cp_wait0();
    convert_group(sm, sbase, raw_off, aseg0, gt);
    __syncthreads();   // covers W/bias init + all groups' first convert

    // Bias fragments -> registers. With the permutation, lane q owns output
    // columns colw + 16k + 4q + {0..3} for each 16-block k.
    const int o_half = wn >> 1;
    const int q = lane & 3;
    float bF[4][4];
    {
        const float* bias_sm = reinterpret_cast<const float*>(sm + SM_BIAS);
        #pragma unroll
        for (int k = 0; k < 4; k++)
            #pragma unroll
            for (int j = 0; j < 4; j++)
                bF[k][j] = bias_sm[(o_half << 7) + (wn & 1) * 64 + 16 * k + 4 * q + j];
    }

    const size_t out_half = (size_t)BATCH * DDIM;
    const int barid = 1 + wm;

    int cur = 0;
    for (int i = 0; i < nt; i++){
        const int  t   = bid + i * grid;
        const bool nxt = (i + 1) < nt;

        // Kick next tile's async copy NOW: the copy engine runs under the whole K-loop.
        if (nxt) issue_cp_group(state, t + grid, wm, gt, raw_base);

        const uint32_t bA = sbase + aseg0 + (uint32_t)cur * ASEG + aoff;

        float acc[2][8][4];
        #pragma unroll
        for (int mt = 0; mt < 2; mt++)
            #pragma unroll
            for (int nj = 0; nj < 8; nj++)
                #pragma unroll
                for (int e = 0; e < 4; e++) acc[mt][nj][e] = 0.f;

        // ---- K loop: 8 steps of k16, single fp16 term ----
        #pragma unroll
        for (int ks = 0; ks < 8; ks++){
            uint32_t a0[4], a1[4];
            ldsm4(a0, bA + ks * 32);
            ldsm4(a1, bA + 16 * PITCH + ks * 32);
            #pragma unroll
            for (int np = 0; np < 4; np++){        // pairs of n8 tiles
                uint32_t bw[4];
                ldsm4(bw, baseB + (uint32_t)(np * 16) * PITCH + ks * 32);
                mma16816(acc[0][2*np],   a0, bw[0], bw[1]);
                mma16816(acc[1][2*np],   a1, bw[0], bw[1]);
                mma16816(acc[0][2*np+1], a0, bw[2], bw[3]);
                mma16816(acc[1][2*np+1], a1, bw[2], bw[3]);
            }
        }

        // ---- convert + barrier FIRST: BAR.SYNC is defer-blocking on sm_103a, so the
        //      epilogue STGs below execute during the barrier wait; the block only
        //      fires at the next K-loop's first LDSM (which needs the protected smem).
        if (nxt){
            cp_wait0();                                           // copy finished under K-loop
            convert_group(sm, sbase, raw_off, aseg0 + (uint32_t)(cur ^ 1) * ASEG, gt);
            group_bar(barid);
        }

        // ---- epilogue: bias + STG.128 (permuted B makes each lane's 4 values 16B-contig). ----
        {
            const int colw  = (wn & 1) * 64;
            const int rbase = wm * 32 + (lane >> 2);
            float* outp = out + (o_half ? out_half : 0) + ((size_t)t * TILE_M) * DDIM;
            #pragma unroll
            for (int mt = 0; mt < 2; mt++){
                #pragma unroll
                for (int h = 0; h < 2; h++){       // h=0: c0c1 rows g; h=1: c2c3 rows g+8
                    float* rowp = outp + (size_t)(rbase + mt * 16 + h * 8) * DDIM + colw + 4 * q;
                    #pragma unroll
                    for (int k = 0; k < 4; k++){
                        float4 val = make_float4(acc[mt][2*k  ][2*h]     + bF[k][0],
                                                 acc[mt][2*k  ][2*h + 1] + bF[k][1],
                                                 acc[mt][2*k+1][2*h]     + bF[k][2],
                                                 acc[mt][2*k+1][2*h + 1] + bF[k][3]);
                        *reinterpret_cast<float4*>(rowp + 16 * k) = val;
                    }
                }
            }
        }

        cur ^= 1;
    }
}

extern "C" void kernel_launch(void* const* d_in, const int* in_sizes, int n_in,
                              void* d_out, int out_size){
    (void)in_sizes; (void)n_in; (void)out_size;
    const float* state = (const float*)d_in[0];
    const float* W     = (const float*)d_in[1];
    const float* b     = (const float*)d_in[2];
    float* out = (float*)d_out;

    int dev = 0, sms = 148;
    cudaGetDevice(&dev);
    cudaDeviceGetAttribute(&sms, cudaDevAttrMultiProcessorCount, dev);
    if (sms < 1) sms = 148;
    if (sms > NTILES) sms = NTILES;

    cudaFuncSetAttribute(lfm_kernel, cudaFuncAttributeMaxDynamicSharedMemorySize, SMEM_TOTAL);
    lfm_kernel<<<sms, THREADS, SMEM_TOTAL>>>(state, W, b, out);
}